// round 6
// baseline (speedup 1.0000x reference)
#include <cuda_runtime.h>
#include <cstdint>

#define THREADS 256
#define ROWS_PER_BLOCK 1024

__device__ __forceinline__ uint32_t smem_u32(const void* p) {
    return (uint32_t)__cvta_generic_to_shared(p);
}

__global__ __launch_bounds__(THREADS, 8)
void mlp321_kernel(const float* __restrict__ x,
                   const float* __restrict__ W1, const float* __restrict__ b1,
                   const float* __restrict__ W2, const float* __restrict__ b2,
                   const float* __restrict__ W3, const float* __restrict__ b3,
                   float* __restrict__ out,     // [B]
                   float* __restrict__ h1_out,  // [B,3]
                   float* __restrict__ h2_out)  // [B,2]
{
    __shared__ __align__(16) float s_out[ROWS_PER_BLOCK];        //  4 KB
    __shared__ __align__(16) float s_h1[ROWS_PER_BLOCK * 3];     // 12 KB
    __shared__ __align__(16) float s_h2[ROWS_PER_BLOCK * 2];     //  8 KB

    int tid = threadIdx.x;
    long long base = (long long)blockIdx.x * ROWS_PER_BLOCK;

    // tiny weights: broadcast L1 hits
    float w1[6], bb1[3], w2[6], bb2[2], w3[2], bb3;
#pragma unroll
    for (int i = 0; i < 6; i++) w1[i] = __ldg(W1 + i);
#pragma unroll
    for (int i = 0; i < 3; i++) bb1[i] = __ldg(b1 + i);
#pragma unroll
    for (int i = 0; i < 6; i++) w2[i] = __ldg(W2 + i);
#pragma unroll
    for (int i = 0; i < 2; i++) bb2[i] = __ldg(b2 + i);
#pragma unroll
    for (int i = 0; i < 2; i++) w3[i] = __ldg(W3 + i);
    bb3 = __ldg(b3);

    // thread t handles 4 consecutive rows 4t..4t+3 (within block)
    int r0 = tid * 4;

    // ---- load 4 rows of x: 8 floats = 2x LDG.128, fully coalesced ----
    const float4* xv = reinterpret_cast<const float4*>(x + (base + r0) * 2);
    float4 xa = __ldg(xv + 0);
    float4 xb = __ldg(xv + 1);
    float x0[4] = {xa.x, xa.z, xb.x, xb.z};
    float x1[4] = {xa.y, xa.w, xb.y, xb.w};

    float h1v[4][3], h2v[4][2], ov[4];

#pragma unroll
    for (int e = 0; e < 4; e++) {
#pragma unroll
        for (int j = 0; j < 3; j++) {
            float v = fmaf(x0[e], w1[j * 2 + 0], fmaf(x1[e], w1[j * 2 + 1], bb1[j]));
            h1v[e][j] = fmaxf(v, 0.0f);
        }
#pragma unroll
        for (int j = 0; j < 2; j++) {
            float v = bb2[j];
#pragma unroll
            for (int k = 0; k < 3; k++) v = fmaf(h1v[e][k], w2[j * 3 + k], v);
            h2v[e][j] = fmaxf(v, 0.0f);
        }
        float z = fmaf(h2v[e][0], w3[0], fmaf(h2v[e][1], w3[1], bb3));
        ov[e] = 1.0f / (1.0f + __expf(-z));
    }

    // ---- all-vector STS: 6x STS.128 per thread ----
    // out: word 4t (lane phase covers all 32 banks — conflict-free)
    reinterpret_cast<float4*>(s_out + r0)[0] = make_float4(ov[0], ov[1], ov[2], ov[3]);

    // h1: words 12t..12t+11 (stride-48B: each 8-lane phase covers all 32 banks)
    float4* h1p = reinterpret_cast<float4*>(s_h1 + r0 * 3);
    h1p[0] = make_float4(h1v[0][0], h1v[0][1], h1v[0][2], h1v[1][0]);
    h1p[1] = make_float4(h1v[1][1], h1v[1][2], h1v[2][0], h1v[2][1]);
    h1p[2] = make_float4(h1v[2][2], h1v[3][0], h1v[3][1], h1v[3][2]);

    // h2: words 8t..8t+7 (2-way conflict, acceptable)
    float4* h2p = reinterpret_cast<float4*>(s_h2 + r0 * 2);
    h2p[0] = make_float4(h2v[0][0], h2v[0][1], h2v[1][0], h2v[1][1]);
    h2p[1] = make_float4(h2v[2][0], h2v[2][1], h2v[3][0], h2v[3][1]);

    // make generic-proxy smem writes visible to the async (TMA) proxy
    asm volatile("fence.proxy.async.shared::cta;" ::: "memory");
    __syncthreads();

    // spread the 3 bulk stores across 3 warps (parallel issue, one commit each)
    if (tid == 0) {
        uint32_t s1 = smem_u32(s_h1);
        asm volatile(
            "cp.async.bulk.global.shared::cta.bulk_group [%0], [%1], %2;"
            :: "l"(h1_out + base * 3), "r"(s1), "r"((uint32_t)(ROWS_PER_BLOCK * 12)) : "memory");
        asm volatile("cp.async.bulk.commit_group;" ::: "memory");
        asm volatile("cp.async.bulk.wait_group.read 0;" ::: "memory");
    } else if (tid == 32) {
        uint32_t s2 = smem_u32(s_h2);
        asm volatile(
            "cp.async.bulk.global.shared::cta.bulk_group [%0], [%1], %2;"
            :: "l"(h2_out + base * 2), "r"(s2), "r"((uint32_t)(ROWS_PER_BLOCK * 8)) : "memory");
        asm volatile("cp.async.bulk.commit_group;" ::: "memory");
        asm volatile("cp.async.bulk.wait_group.read 0;" ::: "memory");
    } else if (tid == 64) {
        uint32_t so = smem_u32(s_out);
        asm volatile(
            "cp.async.bulk.global.shared::cta.bulk_group [%0], [%1], %2;"
            :: "l"(out + base), "r"(so), "r"((uint32_t)(ROWS_PER_BLOCK * 4)) : "memory");
        asm volatile("cp.async.bulk.commit_group;" ::: "memory");
        asm volatile("cp.async.bulk.wait_group.read 0;" ::: "memory");
    }
}

extern "C" void kernel_launch(void* const* d_in, const int* in_sizes, int n_in,
                              void* d_out, int out_size)
{
    const float* x  = (const float*)d_in[0];
    const float* W1 = (const float*)d_in[1];
    const float* b1 = (const float*)d_in[2];
    const float* W2 = (const float*)d_in[3];
    const float* b2 = (const float*)d_in[4];
    const float* W3 = (const float*)d_in[5];
    const float* b3 = (const float*)d_in[6];

    int B = in_sizes[0] / 2;   // x is [B,2]
    float* out    = (float*)d_out;                 // [B]
    float* h1_out = out + B;                       // [B,3]
    float* h2_out = h1_out + (long long)B * 3;     // [B,2]

    int blocks = B / ROWS_PER_BLOCK;               // 8388608 / 1024 = 8192
    mlp321_kernel<<<blocks, THREADS>>>(x, W1, b1, W2, b2, W3, b3,
                                       out, h1_out, h2_out);
}